// round 3
// baseline (speedup 1.0000x reference)
#include <cuda_runtime.h>
#include <math.h>

#define BB   8
#define SS   2048
#define VV   32000
#define DD   512
#define KK   256      // n_kernels (feature channels)
#define JJ   9        // conv kernel size
#define CC   4096     // n_classes
#define PADW 4

// ---- static device scratch (allocation-free rule) ----
__device__ float g_xemb  [(size_t)BB*SS*DD];   // 32 MB  gathered embeddings
__device__ float g_wt    [(size_t)JJ*DD*KK];   // 4.5 MB conv weights transposed [j][d][k]
__device__ float g_xfeat [(size_t)BB*SS*KK];   // 16 MB  tanh(conv)+bias
__device__ float g_scores[(size_t)BB*CC*SS];   // 256 MB attention logits
__device__ float g_stats [(size_t)BB*CC*2];    // rowmax, rowsumexp
__device__ float g_m     [(size_t)BB*CC*KK];   // 32 MB  attended features

// ---------------------------------------------------------------------------
// 1) Embedding gather: g_xemb[b,s,:] = table[text[b,s],:]   (float4 vectorized)
// ---------------------------------------------------------------------------
__global__ void k_gather(const int* __restrict__ text, const float* __restrict__ table) {
    int idx = blockIdx.x * blockDim.x + threadIdx.x;
    const int total = BB * SS * (DD / 4);
    if (idx >= total) return;
    int d4 = idx & (DD/4 - 1);      // DD/4 = 128
    int bs = idx >> 7;
    int tok = text[bs];
    reinterpret_cast<float4*>(g_xemb)[(size_t)bs * (DD/4) + d4] =
        reinterpret_cast<const float4*>(table)[(size_t)tok * (DD/4) + d4];
}

// ---------------------------------------------------------------------------
// 2) Weight transpose: conv_w[k][d][j] -> g_wt[j][d][k]  (coalesced k writes)
// ---------------------------------------------------------------------------
__global__ void k_wtrans(const float* __restrict__ w) {
    int idx = blockIdx.x * blockDim.x + threadIdx.x;
    if (idx >= JJ * DD * KK) return;
    int k = idx % KK;
    int d = (idx / KK) % DD;
    int j = idx / (KK * DD);
    g_wt[idx] = w[((size_t)k * DD + d) * JJ + j];
}

// ---------------------------------------------------------------------------
// 3) Conv1d + bias + tanh -> g_xfeat[b][s][k]
//    Block tile: 64 s x 64 k, 256 threads, 4x4 microtile, d-chunks of 16.
// ---------------------------------------------------------------------------
#define CTS 64
#define CTK 64
#define CDC 16

__global__ __launch_bounds__(256) void k_conv(const float* __restrict__ convb) {
    __shared__ float xs[CTS + 8][CDC + 1];      // 72 x 17  (padded vs conflicts)
    __shared__ float ws[JJ][CDC][CTK];          // 9 x 16 x 64 = 36 KB

    const int tid = threadIdx.x;
    const int s0  = blockIdx.x * CTS;
    const int k0  = blockIdx.y * CTK;
    const int b   = blockIdx.z;
    const int tx  = tid & 15;     // k quad index
    const int ty  = tid >> 4;     // s quad index

    float acc[4][4];
    #pragma unroll
    for (int i = 0; i < 4; i++)
        #pragma unroll
        for (int l = 0; l < 4; l++) acc[i][l] = 0.f;

    const float* xemb_b = g_xemb + (size_t)b * SS * DD;

    for (int d0 = 0; d0 < DD; d0 += CDC) {
        // stage x tile (72 rows x 16 d), zero-padded at sequence edges
        for (int idx = tid; idx < (CTS + 8) * CDC; idx += 256) {
            int d = idx & (CDC - 1);
            int row = idx >> 4;
            int r = s0 - PADW + row;
            xs[row][d] = (r >= 0 && r < SS) ? xemb_b[(size_t)r * DD + d0 + d] : 0.f;
        }
        // stage all 9 tap weight slices for this d-chunk
        for (int idx = tid; idx < JJ * CDC * CTK; idx += 256) {
            int k = idx & 63;
            int d = (idx >> 6) & 15;
            int j = idx >> 10;
            ws[j][d][k] = g_wt[((size_t)j * DD + d0 + d) * KK + k0 + k];
        }
        __syncthreads();

        for (int j = 0; j < JJ; j++) {
            #pragma unroll
            for (int d = 0; d < CDC; d++) {
                float4 wv = *reinterpret_cast<const float4*>(&ws[j][d][tx * 4]);
                #pragma unroll
                for (int i = 0; i < 4; i++) {
                    float xv = xs[ty * 4 + i + j][d];
                    acc[i][0] += xv * wv.x;
                    acc[i][1] += xv * wv.y;
                    acc[i][2] += xv * wv.z;
                    acc[i][3] += xv * wv.w;
                }
            }
        }
        __syncthreads();
    }

    float bias0 = convb[k0 + tx*4 + 0];
    float bias1 = convb[k0 + tx*4 + 1];
    float bias2 = convb[k0 + tx*4 + 2];
    float bias3 = convb[k0 + tx*4 + 3];
    #pragma unroll
    for (int i = 0; i < 4; i++) {
        int s = s0 + ty * 4 + i;
        float4 o;
        o.x = tanhf(acc[i][0] + bias0);
        o.y = tanhf(acc[i][1] + bias1);
        o.z = tanhf(acc[i][2] + bias2);
        o.w = tanhf(acc[i][3] + bias3);
        *reinterpret_cast<float4*>(&g_xfeat[((size_t)b * SS + s) * KK + k0 + tx * 4]) = o;
    }
}

// ---------------------------------------------------------------------------
// 4) scores[b][c][s] = sum_k U[c][k] * xfeat[b][s][k]
//    NT GEMM, tile 64c x 64s, k-chunks of 16, 4x4 microtile with float4 LDS.
// ---------------------------------------------------------------------------
__global__ __launch_bounds__(256) void k_scores(const float* __restrict__ Uw) {
    __shared__ float Us[16][68];
    __shared__ float Xs[16][68];
    const int tid = threadIdx.x;
    const int s0 = blockIdx.x * 64;
    const int c0 = blockIdx.y * 64;
    const int b  = blockIdx.z;
    const int tx = tid & 15;   // c quad
    const int ty = tid >> 4;   // s quad

    float acc[4][4];
    #pragma unroll
    for (int i = 0; i < 4; i++)
        #pragma unroll
        for (int l = 0; l < 4; l++) acc[i][l] = 0.f;

    const float* xf = g_xfeat + (size_t)b * SS * KK;

    for (int kk = 0; kk < KK; kk += 16) {
        #pragma unroll
        for (int t = 0; t < 4; t++) {
            int idx = tid + t * 256;
            int kcol = idx & 15;
            int r    = idx >> 4;
            Us[kcol][r] = Uw[(size_t)(c0 + r) * KK + kk + kcol];
            Xs[kcol][r] = xf[(size_t)(s0 + r) * KK + kk + kcol];
        }
        __syncthreads();
        #pragma unroll
        for (int d = 0; d < 16; d++) {
            float4 cv = *reinterpret_cast<const float4*>(&Us[d][tx * 4]);
            float4 sv = *reinterpret_cast<const float4*>(&Xs[d][ty * 4]);
            acc[0][0] += cv.x * sv.x; acc[0][1] += cv.x * sv.y; acc[0][2] += cv.x * sv.z; acc[0][3] += cv.x * sv.w;
            acc[1][0] += cv.y * sv.x; acc[1][1] += cv.y * sv.y; acc[1][2] += cv.y * sv.z; acc[1][3] += cv.y * sv.w;
            acc[2][0] += cv.z * sv.x; acc[2][1] += cv.z * sv.y; acc[2][2] += cv.z * sv.z; acc[2][3] += cv.z * sv.w;
            acc[3][0] += cv.w * sv.x; acc[3][1] += cv.w * sv.y; acc[3][2] += cv.w * sv.z; acc[3][3] += cv.w * sv.w;
        }
        __syncthreads();
    }

    #pragma unroll
    for (int ci = 0; ci < 4; ci++) {
        float4 o = make_float4(acc[ci][0], acc[ci][1], acc[ci][2], acc[ci][3]);
        *reinterpret_cast<float4*>(
            &g_scores[((size_t)b * CC + c0 + tx * 4 + ci) * SS + s0 + ty * 4]) = o;
    }
}

// ---------------------------------------------------------------------------
// 5) Per-(b,c) row max + sum(exp) over S
// ---------------------------------------------------------------------------
__global__ void k_stats() {
    __shared__ float red[256];
    const int row = blockIdx.x;                 // row = b*CC + c
    const float* p = g_scores + (size_t)row * SS;
    const int tid = threadIdx.x;

    float mx = -1e30f;
    for (int i = tid; i < SS; i += 256) mx = fmaxf(mx, p[i]);
    red[tid] = mx; __syncthreads();
    for (int o = 128; o > 0; o >>= 1) {
        if (tid < o) red[tid] = fmaxf(red[tid], red[tid + o]);
        __syncthreads();
    }
    mx = red[0]; __syncthreads();

    float sm = 0.f;
    for (int i = tid; i < SS; i += 256) sm += __expf(p[i] - mx);
    red[tid] = sm; __syncthreads();
    for (int o = 128; o > 0; o >>= 1) {
        if (tid < o) red[tid] += red[tid + o];
        __syncthreads();
    }
    if (tid == 0) {
        g_stats[(size_t)row * 2 + 0] = mx;
        g_stats[(size_t)row * 2 + 1] = red[0];
    }
}

// ---------------------------------------------------------------------------
// 6) m[b][c][k] = sum_s softmax(scores)[b][c][s] * xfeat[b][s][k]
//    GEMM with on-the-fly exp() on the A tile, 1/l scaling in epilogue.
// ---------------------------------------------------------------------------
__global__ __launch_bounds__(256) void k_mgemm() {
    __shared__ float As[16][68];
    __shared__ float Bs[16][68];
    __shared__ float mxs[64];
    __shared__ float lss[64];
    const int tid = threadIdx.x;
    const int k0 = blockIdx.x * 64;
    const int c0 = blockIdx.y * 64;
    const int b  = blockIdx.z;
    if (tid < 64) {
        mxs[tid] = g_stats[((size_t)b * CC + c0 + tid) * 2 + 0];
        lss[tid] = g_stats[((size_t)b * CC + c0 + tid) * 2 + 1];
    }
    __syncthreads();

    const int tx = tid & 15;   // c quad
    const int ty = tid >> 4;   // k quad
    float acc[4][4];
    #pragma unroll
    for (int i = 0; i < 4; i++)
        #pragma unroll
        for (int l = 0; l < 4; l++) acc[i][l] = 0.f;

    const float* sc = g_scores + ((size_t)b * CC + c0) * SS;
    const float* xf = g_xfeat + (size_t)b * SS * KK;

    for (int ss = 0; ss < SS; ss += 16) {
        #pragma unroll
        for (int t = 0; t < 4; t++) {
            int idx = tid + t * 256;
            int scol = idx & 15;
            int c    = idx >> 4;
            As[scol][c] = __expf(sc[(size_t)c * SS + ss + scol] - mxs[c]);
            int kc   = idx & 63;
            int srow = idx >> 6;
            Bs[srow][kc] = xf[(size_t)(ss + srow) * KK + k0 + kc];
        }
        __syncthreads();
        #pragma unroll
        for (int s = 0; s < 16; s++) {
            float4 av = *reinterpret_cast<const float4*>(&As[s][tx * 4]);
            float4 bv = *reinterpret_cast<const float4*>(&Bs[s][ty * 4]);
            acc[0][0] += av.x * bv.x; acc[0][1] += av.x * bv.y; acc[0][2] += av.x * bv.z; acc[0][3] += av.x * bv.w;
            acc[1][0] += av.y * bv.x; acc[1][1] += av.y * bv.y; acc[1][2] += av.y * bv.z; acc[1][3] += av.y * bv.w;
            acc[2][0] += av.z * bv.x; acc[2][1] += av.z * bv.y; acc[2][2] += av.z * bv.z; acc[2][3] += av.z * bv.w;
            acc[3][0] += av.w * bv.x; acc[3][1] += av.w * bv.y; acc[3][2] += av.w * bv.z; acc[3][3] += av.w * bv.w;
        }
        __syncthreads();
    }

    #pragma unroll
    for (int ci = 0; ci < 4; ci++) {
        float rl = 1.f / lss[tx * 4 + ci];
        float4 o = make_float4(acc[ci][0] * rl, acc[ci][1] * rl,
                               acc[ci][2] * rl, acc[ci][3] * rl);
        *reinterpret_cast<float4*>(
            &g_m[((size_t)b * CC + c0 + tx * 4 + ci) * KK + k0 + ty * 4]) = o;
    }
}

// ---------------------------------------------------------------------------
// 7) y[b][c] = dot(final_w[c], m[b][c]) + final_b[c]   (warp per output)
// ---------------------------------------------------------------------------
__global__ void k_final(const float* __restrict__ fw, const float* __restrict__ fb,
                        float* __restrict__ out) {
    int gwarp = (blockIdx.x * blockDim.x + threadIdx.x) >> 5;
    int lane  = threadIdx.x & 31;
    if (gwarp >= BB * CC) return;
    int c = gwarp % CC;
    const float* m = g_m + (size_t)gwarp * KK;
    const float* w = fw + (size_t)c * KK;
    float acc = 0.f;
    #pragma unroll
    for (int k = lane; k < KK; k += 32) acc += w[k] * m[k];
    #pragma unroll
    for (int o = 16; o > 0; o >>= 1) acc += __shfl_down_sync(0xffffffff, acc, o);
    if (lane == 0) out[gwarp] = acc + fb[c];
}

// ---------------------------------------------------------------------------
extern "C" void kernel_launch(void* const* d_in, const int* in_sizes, int n_in,
                              void* d_out, int out_size) {
    const int*   text  = (const int*)  d_in[0];
    const float* table = (const float*)d_in[1];
    const float* convw = (const float*)d_in[2];
    const float* convb = (const float*)d_in[3];
    const float* Uw    = (const float*)d_in[4];
    const float* fw    = (const float*)d_in[5];
    const float* fb    = (const float*)d_in[6];
    float* out = (float*)d_out;

    k_gather<<<(BB*SS*(DD/4) + 255) / 256, 256>>>(text, table);
    k_wtrans<<<(JJ*DD*KK + 255) / 256, 256>>>(convw);
    k_conv  <<<dim3(SS/CTS, KK/CTK, BB), 256>>>(convb);
    k_scores<<<dim3(SS/64, CC/64, BB), 256>>>(Uw);
    k_stats <<<BB*CC, 256>>>();
    k_mgemm <<<dim3(KK/64, CC/64, BB), 256>>>();
    k_final <<<(BB*CC*32) / 256, 256>>>(fw, fb, out);
}

// round 5
// speedup vs baseline: 5.8965x; 5.8965x over previous
#include <cuda_runtime.h>
#include <cuda_bf16.h>
#include <math.h>
#include <stdint.h>

#define BB   8
#define SSL  2048
#define DD   512
#define KF   256      // n_kernels
#define JJ   9
#define CC   4096
#define PADW 4

// ---------------- static device scratch (allocation-free rule) ----------------
__device__ __nv_bfloat16 g_xemb [(size_t)BB*SSL*DD];   // 16 MB
__device__ __nv_bfloat16 g_wtT  [(size_t)JJ*KF*DD];    // 2.25 MB [j][k][d]
__device__ __nv_bfloat16 g_Ubf  [(size_t)CC*KF];       // 2 MB
__device__ __nv_bfloat16 g_xf   [(size_t)BB*SSL*KF];   // 8 MB  [b][s][k]
__device__ __nv_bfloat16 g_xfT  [(size_t)BB*KF*SSL];   // 8 MB  [b][k][s]
__device__ __nv_bfloat16 g_sc   [(size_t)BB*CC*SSL];   // 128 MB scores -> alpha (in place)
__device__ float         g_l    [(size_t)BB*CC];       // softmax denominators
__device__ float         g_m    [(size_t)BB*CC*KF];    // 32 MB

// ---------------- PTX helpers (base-ISA only) ----------------
__device__ __forceinline__ uint32_t smem_u32(const void* p) {
    uint32_t a;
    asm("{ .reg .u64 t; cvta.to.shared.u64 t, %1; cvt.u32.u64 %0, t; }" : "=r"(a) : "l"(p));
    return a;
}
__device__ __forceinline__ void ldsm_x4(uint32_t& r0, uint32_t& r1, uint32_t& r2, uint32_t& r3,
                                        uint32_t addr) {
    asm volatile("ldmatrix.sync.aligned.m8n8.x4.shared.b16 {%0,%1,%2,%3}, [%4];"
                 : "=r"(r0), "=r"(r1), "=r"(r2), "=r"(r3) : "r"(addr));
}
__device__ __forceinline__ void mma_bf16(float* c, uint32_t a0, uint32_t a1, uint32_t a2,
                                         uint32_t a3, uint32_t b0, uint32_t b1) {
    asm volatile("mma.sync.aligned.m16n8k16.row.col.f32.bf16.bf16.f32 "
                 "{%0,%1,%2,%3}, {%4,%5,%6,%7}, {%8,%9}, {%0,%1,%2,%3};"
                 : "+f"(c[0]), "+f"(c[1]), "+f"(c[2]), "+f"(c[3])
                 : "r"(a0), "r"(a1), "r"(a2), "r"(a3), "r"(b0), "r"(b1));
}
#define CPA(dst, src, sz) \
    asm volatile("cp.async.ca.shared.global [%0], [%1], 16, %2;" \
                 :: "r"(dst), "l"(src), "r"(sz) : "memory")
#define CP_COMMIT() asm volatile("cp.async.commit_group;" ::: "memory")
#define CP_WAIT1()  asm volatile("cp.async.wait_group 1;" ::: "memory")
#define CP_WAIT0()  asm volatile("cp.async.wait_group 0;" ::: "memory")

// smem tile geometry: [128 rows][32 k] bf16, padded stride 40 (80B -> conflict-free ldmatrix)
#define TSTRIDE 40

// shared 8-warp GEMM chunk: 128M x 128N x 32K, warp = 32M x 64N
__device__ __forceinline__ void gemm_chunk(uint32_t aA, uint32_t aB, int wm, int wn, int lane,
                                           float (*acc)[8][4]) {
    const int lrow = (lane & 7) + ((lane >> 3) & 1) * 8;
    const int lcol = ((lane >> 4) & 1) * 8;
    #pragma unroll
    for (int ks = 0; ks < 2; ks++) {
        uint32_t a[2][4];
        #pragma unroll
        for (int mt = 0; mt < 2; mt++)
            ldsm_x4(a[mt][0], a[mt][1], a[mt][2], a[mt][3],
                    aA + (((wm + mt * 16 + lrow) * TSTRIDE) + ks * 16 + lcol) * 2);
        #pragma unroll
        for (int nt = 0; nt < 4; nt++) {
            uint32_t b0, b1, b2, b3;
            ldsm_x4(b0, b1, b2, b3,
                    aB + (((wn + nt * 16 + lrow) * TSTRIDE) + ks * 16 + lcol) * 2);
            #pragma unroll
            for (int mt = 0; mt < 2; mt++) {
                mma_bf16(acc[mt][nt * 2 + 0], a[mt][0], a[mt][1], a[mt][2], a[mt][3], b0, b2);
                mma_bf16(acc[mt][nt * 2 + 1], a[mt][0], a[mt][1], a[mt][2], a[mt][3], b1, b3);
            }
        }
    }
}

// fast e^x on FMA pipe (no MUFU): 2^(x*log2e), deg-4 poly on [-0.5, 0.5]
__device__ __forceinline__ float fast_exp(float x) {
    float y = x * 1.44269504089f;
    float n = rintf(y);
    float f = y - n;
    float p = 0.0096180489f;
    p = fmaf(p, f, 0.0555041087f);
    p = fmaf(p, f, 0.2402265069f);
    p = fmaf(p, f, 0.6931471806f);
    p = fmaf(p, f, 1.0f);
    int ni = (int)n;
    if (ni < -126) ni = -126;
    return __int_as_float((ni + 127) << 23) * p;
}

// ---------------- prep kernels ----------------
__global__ void k_gather(const int* __restrict__ text, const float* __restrict__ table) {
    int idx = blockIdx.x * blockDim.x + threadIdx.x;
    const int total = BB * SSL * (DD / 4);
    if (idx >= total) return;
    int d4 = idx & (DD / 4 - 1);
    int bs = idx >> 7;
    int tok = text[bs];
    float4 v = reinterpret_cast<const float4*>(table)[(size_t)tok * (DD / 4) + d4];
    __nv_bfloat162 h0 = __floats2bfloat162_rn(v.x, v.y);
    __nv_bfloat162 h1 = __floats2bfloat162_rn(v.z, v.w);
    uint2 o = make_uint2(*(uint32_t*)&h0, *(uint32_t*)&h1);
    *reinterpret_cast<uint2*>(g_xemb + (size_t)bs * DD + d4 * 4) = o;
}
__global__ void k_wprep(const float* __restrict__ w) {
    int idx = blockIdx.x * blockDim.x + threadIdx.x;
    if (idx >= JJ * KF * DD) return;
    int d = idx % DD;
    int k = (idx / DD) % KF;
    int j = idx / (DD * KF);
    g_wtT[idx] = __float2bfloat16(w[((size_t)k * DD + d) * JJ + j]);
}
__global__ void k_uprep(const float* __restrict__ u) {
    int idx = blockIdx.x * blockDim.x + threadIdx.x;
    if (idx >= CC * KF) return;
    g_Ubf[idx] = __float2bfloat16(u[idx]);
}

// ---------------- 1) conv as implicit GEMM ----------------
__global__ __launch_bounds__(256) void k_conv_mma(const float* __restrict__ convb) {
    __shared__ __align__(16) __nv_bfloat16 As[2][128 * TSTRIDE];
    __shared__ __align__(16) __nv_bfloat16 Bs[2][128 * TSTRIDE];
    __shared__ float sbias[128];

    const int tid = threadIdx.x, wid = tid >> 5, lane = tid & 31;
    const int s0 = blockIdx.x * 128, k0 = blockIdx.y * 128, b = blockIdx.z;
    const int wm = (wid & 3) * 32, wn = (wid >> 2) * 64;
    if (tid < 128) sbias[tid] = convb[k0 + tid];

    uint32_t aAb[2] = { smem_u32(&As[0][0]), smem_u32(&As[1][0]) };
    uint32_t aBb[2] = { smem_u32(&Bs[0][0]), smem_u32(&Bs[1][0]) };

    float acc[2][8][4] = {};

    auto load_chunk = [&](int ch, int buf) {
        int j = ch >> 4, dc = ch & 15;     // ch = j*16 + dchunk
        #pragma unroll
        for (int it = 0; it < 2; it++) {
            int i = tid + it * 256;
            int row = i >> 2, cs = i & 3;
            uint32_t doff = (row * TSTRIDE + cs * 8) * 2;
            int g = s0 + row + j - PADW;
            unsigned ok = ((unsigned)g < SSL);
            const void* sA = g_xemb + ((size_t)b * SSL + (ok ? g : 0)) * DD + dc * 32 + cs * 8;
            CPA(aAb[buf] + doff, sA, ok ? 16u : 0u);
            const void* sB = g_wtT + ((size_t)j * KF + k0 + row) * DD + dc * 32 + cs * 8;
            CPA(aBb[buf] + doff, sB, 16u);
        }
    };

    const int NC = JJ * (DD / 32);     // 144
    load_chunk(0, 0); CP_COMMIT();
    for (int ch = 0; ch < NC; ch++) {
        if (ch + 1 < NC) { load_chunk(ch + 1, (ch + 1) & 1); CP_COMMIT(); CP_WAIT1(); }
        else CP_WAIT0();
        __syncthreads();
        gemm_chunk(aAb[ch & 1], aBb[ch & 1], wm, wn, lane, acc);
        __syncthreads();
    }

    const int lr = lane >> 2, lc = (lane & 3) * 2;
    #pragma unroll
    for (int mt = 0; mt < 2; mt++)
        #pragma unroll
        for (int h = 0; h < 2; h++) {
            int s = s0 + wm + mt * 16 + lr + h * 8;
            __nv_bfloat16* orow = g_xf + ((size_t)b * SSL + s) * KF + k0;
            #pragma unroll
            for (int nt = 0; nt < 8; nt++) {
                int kc = wn + nt * 8 + lc;
                __nv_bfloat16 h0 = __float2bfloat16(tanhf(acc[mt][nt][h * 2 + 0] + sbias[kc]));
                __nv_bfloat16 h1 = __float2bfloat16(tanhf(acc[mt][nt][h * 2 + 1] + sbias[kc + 1]));
                __nv_bfloat162 hh; hh.x = h0; hh.y = h1;
                *reinterpret_cast<uint32_t*>(orow + kc) = *(uint32_t*)&hh;
                g_xfT[((size_t)b * KF + k0 + kc) * SSL + s] = h0;
                g_xfT[((size_t)b * KF + k0 + kc + 1) * SSL + s] = h1;
            }
        }
}

// ---------------- 2) scores = U @ xf^T -> bf16 ----------------
__global__ __launch_bounds__(256) void k_scores_mma() {
    __shared__ __align__(16) __nv_bfloat16 As[2][128 * TSTRIDE];
    __shared__ __align__(16) __nv_bfloat16 Bs[2][128 * TSTRIDE];

    const int tid = threadIdx.x, wid = tid >> 5, lane = tid & 31;
    const int s0 = blockIdx.x * 128, c0 = blockIdx.y * 128, b = blockIdx.z;
    const int wm = (wid & 3) * 32, wn = (wid >> 2) * 64;

    uint32_t aAb[2] = { smem_u32(&As[0][0]), smem_u32(&As[1][0]) };
    uint32_t aBb[2] = { smem_u32(&Bs[0][0]), smem_u32(&Bs[1][0]) };

    float acc[2][8][4] = {};

    auto load_chunk = [&](int ch, int buf) {
        #pragma unroll
        for (int it = 0; it < 2; it++) {
            int i = tid + it * 256;
            int row = i >> 2, cs = i & 3;
            uint32_t doff = (row * TSTRIDE + cs * 8) * 2;
            const void* sA = g_Ubf + (size_t)(c0 + row) * KF + ch * 32 + cs * 8;
            CPA(aAb[buf] + doff, sA, 16u);
            const void* sB = g_xf + ((size_t)b * SSL + s0 + row) * KF + ch * 32 + cs * 8;
            CPA(aBb[buf] + doff, sB, 16u);
        }
    };

    const int NC = KF / 32;            // 8
    load_chunk(0, 0); CP_COMMIT();
    for (int ch = 0; ch < NC; ch++) {
        if (ch + 1 < NC) { load_chunk(ch + 1, (ch + 1) & 1); CP_COMMIT(); CP_WAIT1(); }
        else CP_WAIT0();
        __syncthreads();
        gemm_chunk(aAb[ch & 1], aBb[ch & 1], wm, wn, lane, acc);
        __syncthreads();
    }

    const int lr = lane >> 2, lc = (lane & 3) * 2;
    #pragma unroll
    for (int mt = 0; mt < 2; mt++)
        #pragma unroll
        for (int h = 0; h < 2; h++) {
            int c = c0 + wm + mt * 16 + lr + h * 8;
            __nv_bfloat16* orow = g_sc + ((size_t)b * CC + c) * SSL + s0;
            #pragma unroll
            for (int nt = 0; nt < 8; nt++) {
                int sc = wn + nt * 8 + lc;
                __nv_bfloat162 hh = __floats2bfloat162_rn(acc[mt][nt][h * 2 + 0],
                                                          acc[mt][nt][h * 2 + 1]);
                *reinterpret_cast<uint32_t*>(orow + sc) = *(uint32_t*)&hh;
            }
        }
}

// ---------------- 3) row max + in-place expify + row sum ----------------
__global__ void k_stats() {
    __shared__ float red[256];
    const int row = blockIdx.x;
    const int tid = threadIdx.x;
    __nv_bfloat16* p = g_sc + (size_t)row * SSL + tid * 8;
    uint4 v = *reinterpret_cast<const uint4*>(p);
    float x[8];
    {
        uint32_t* u = (uint32_t*)&v;
        #pragma unroll
        for (int w = 0; w < 4; w++) {
            __nv_bfloat162 h = *reinterpret_cast<__nv_bfloat162*>(&u[w]);
            x[2 * w]     = __low2float(h);
            x[2 * w + 1] = __high2float(h);
        }
    }
    float mx = x[0];
    #pragma unroll
    for (int i = 1; i < 8; i++) mx = fmaxf(mx, x[i]);
    red[tid] = mx; __syncthreads();
    for (int o = 128; o > 0; o >>= 1) {
        if (tid < o) red[tid] = fmaxf(red[tid], red[tid + o]);
        __syncthreads();
    }
    mx = red[0]; __syncthreads();

    uint4 o4; uint32_t* ou = (uint32_t*)&o4;
    float sm = 0.f;
    #pragma unroll
    for (int w = 0; w < 4; w++) {
        float e0 = fast_exp(x[2 * w] - mx);
        float e1 = fast_exp(x[2 * w + 1] - mx);
        __nv_bfloat16 b0 = __float2bfloat16(e0);
        __nv_bfloat16 b1 = __float2bfloat16(e1);
        sm += __bfloat162float(b0) + __bfloat162float(b1);   // sum what the GEMM will see
        __nv_bfloat162 hh; hh.x = b0; hh.y = b1;
        ou[w] = *(uint32_t*)&hh;
    }
    *reinterpret_cast<uint4*>(p) = o4;
    red[tid] = sm; __syncthreads();
    for (int o = 128; o > 0; o >>= 1) {
        if (tid < o) red[tid] += red[tid + o];
        __syncthreads();
    }
    if (tid == 0) g_l[row] = red[0];
}

// ---------------- 4) m = alpha @ xfT, scaled by 1/l ----------------
__global__ __launch_bounds__(256) void k_mgemm_mma() {
    __shared__ __align__(16) __nv_bfloat16 As[2][128 * TSTRIDE];
    __shared__ __align__(16) __nv_bfloat16 Bs[2][128 * TSTRIDE];
    __shared__ float s_l[128];

    const int tid = threadIdx.x, wid = tid >> 5, lane = tid & 31;
    const int k0 = blockIdx.x * 128, c0 = blockIdx.y * 128, b = blockIdx.z;
    const int wm = (wid & 3) * 32, wn = (wid >> 2) * 64;
    if (tid < 128) s_l[tid] = g_l[(size_t)b * CC + c0 + tid];

    uint32_t aAb[2] = { smem_u32(&As[0][0]), smem_u32(&As[1][0]) };
    uint32_t aBb[2] = { smem_u32(&Bs[0][0]), smem_u32(&Bs[1][0]) };

    float acc[2][8][4] = {};

    auto load_chunk = [&](int ch, int buf) {
        #pragma unroll
        for (int it = 0; it < 2; it++) {
            int i = tid + it * 256;
            int row = i >> 2, cs = i & 3;
            uint32_t doff = (row * TSTRIDE + cs * 8) * 2;
            const void* sA = g_sc + ((size_t)b * CC + c0 + row) * SSL + ch * 32 + cs * 8;
            CPA(aAb[buf] + doff, sA, 16u);
            const void* sB = g_xfT + ((size_t)b * KF + k0 + row) * SSL + ch * 32 + cs * 8;
            CPA(aBb[buf] + doff, sB, 16u);
        }
    };

    const int NC = SSL / 32;           // 64
    load_chunk(0, 0); CP_COMMIT();
    for (int ch = 0; ch < NC; ch++) {
        if (ch + 1 < NC) { load_chunk(ch + 1, (ch + 1) & 1); CP_COMMIT(); CP_WAIT1(); }
        else CP_WAIT0();
        __syncthreads();
        gemm_chunk(aAb[ch & 1], aBb[ch & 1], wm, wn, lane, acc);
        __syncthreads();
    }

    const int lr = lane >> 2, lc = (lane & 3) * 2;
    #pragma unroll
    for (int mt = 0; mt < 2; mt++)
        #pragma unroll
        for (int h = 0; h < 2; h++) {
            int cidx = wm + mt * 16 + lr + h * 8;
            float rl = 1.f / s_l[cidx];
            float* orow = g_m + ((size_t)b * CC + c0 + cidx) * KF + k0;
            #pragma unroll
            for (int nt = 0; nt < 8; nt++) {
                int kc = wn + nt * 8 + lc;
                float2 o = make_float2(acc[mt][nt][h * 2 + 0] * rl,
                                       acc[mt][nt][h * 2 + 1] * rl);
                *reinterpret_cast<float2*>(orow + kc) = o;
            }
        }
}

// ---------------- 5) final readout ----------------
__global__ void k_final(const float* __restrict__ fw, const float* __restrict__ fb,
                        float* __restrict__ out) {
    int gwarp = (blockIdx.x * blockDim.x + threadIdx.x) >> 5;
    int lane  = threadIdx.x & 31;
    if (gwarp >= BB * CC) return;
    int c = gwarp % CC;
    const float* m = g_m + (size_t)gwarp * KF;
    const float* w = fw + (size_t)c * KF;
    float acc = 0.f;
    #pragma unroll
    for (int k = lane; k < KF; k += 32) acc += w[k] * m[k];
    #pragma unroll
    for (int o = 16; o > 0; o >>= 1) acc += __shfl_down_sync(0xffffffff, acc, o);
    if (lane == 0) out[gwarp] = acc + fb[c];
}

// ---------------------------------------------------------------------------
extern "C" void kernel_launch(void* const* d_in, const int* in_sizes, int n_in,
                              void* d_out, int out_size) {
    const int*   text  = (const int*)  d_in[0];
    const float* table = (const float*)d_in[1];
    const float* convw = (const float*)d_in[2];
    const float* convb = (const float*)d_in[3];
    const float* Uw    = (const float*)d_in[4];
    const float* fw    = (const float*)d_in[5];
    const float* fb    = (const float*)d_in[6];
    float* out = (float*)d_out;

    k_gather<<<(BB*SSL*(DD/4) + 255) / 256, 256>>>(text, table);
    k_wprep <<<(JJ*KF*DD + 255) / 256, 256>>>(convw);
    k_uprep <<<(CC*KF + 255) / 256, 256>>>(Uw);
    k_conv_mma  <<<dim3(SSL/128, KF/128, BB), 256>>>(convb);
    k_scores_mma<<<dim3(SSL/128, CC/128, BB), 256>>>();
    k_stats     <<<BB*CC, 256>>>();
    k_mgemm_mma <<<dim3(KF/128, CC/128, BB), 256>>>();
    k_final     <<<(BB*CC*32) / 256, 256>>>(fw, fb, out);
}

// round 8
// speedup vs baseline: 6.2887x; 1.0665x over previous
#include <cuda_runtime.h>
#include <cuda_bf16.h>
#include <math.h>
#include <stdint.h>

#define BB   8
#define SSL  2048
#define DD   512
#define KF   256      // n_kernels
#define JJ   9
#define CC   4096
#define PADW 4

// ---------------- static device scratch (allocation-free rule) ----------------
__device__ __nv_bfloat16 g_xemb [(size_t)BB*SSL*DD];   // 16 MB
__device__ __nv_bfloat16 g_wtT  [(size_t)JJ*KF*DD];    // 2.25 MB [j][k][d]
__device__ __nv_bfloat16 g_Ubf  [(size_t)CC*KF];       // 2 MB
__device__ __nv_bfloat16 g_xf   [(size_t)BB*SSL*KF];   // 8 MB  [b][s][k]
__device__ __nv_bfloat16 g_sc   [(size_t)BB*CC*SSL];   // 128 MB scores -> alpha (in place)
__device__ float         g_l    [(size_t)BB*CC];       // softmax denominators
__device__ float         g_m    [(size_t)BB*CC*KF];    // 32 MB

// ---------------- PTX helpers (base-ISA only) ----------------
__device__ __forceinline__ uint32_t smem_u32(const void* p) {
    uint32_t a;
    asm("{ .reg .u64 t; cvta.to.shared.u64 t, %1; cvt.u32.u64 %0, t; }" : "=r"(a) : "l"(p));
    return a;
}
__device__ __forceinline__ void ldsm_x4(uint32_t& r0, uint32_t& r1, uint32_t& r2, uint32_t& r3,
                                        uint32_t addr) {
    asm volatile("ldmatrix.sync.aligned.m8n8.x4.shared.b16 {%0,%1,%2,%3}, [%4];"
                 : "=r"(r0), "=r"(r1), "=r"(r2), "=r"(r3) : "r"(addr));
}
__device__ __forceinline__ void ldsm_x4_t(uint32_t& r0, uint32_t& r1, uint32_t& r2, uint32_t& r3,
                                          uint32_t addr) {
    asm volatile("ldmatrix.sync.aligned.m8n8.x4.trans.shared.b16 {%0,%1,%2,%3}, [%4];"
                 : "=r"(r0), "=r"(r1), "=r"(r2), "=r"(r3) : "r"(addr));
}
__device__ __forceinline__ void mma_bf16(float* c, uint32_t a0, uint32_t a1, uint32_t a2,
                                         uint32_t a3, uint32_t b0, uint32_t b1) {
    asm volatile("mma.sync.aligned.m16n8k16.row.col.f32.bf16.bf16.f32 "
                 "{%0,%1,%2,%3}, {%4,%5,%6,%7}, {%8,%9}, {%0,%1,%2,%3};"
                 : "+f"(c[0]), "+f"(c[1]), "+f"(c[2]), "+f"(c[3])
                 : "r"(a0), "r"(a1), "r"(a2), "r"(a3), "r"(b0), "r"(b1));
}
__device__ __forceinline__ float htanh(float x) {
    float y; asm("tanh.approx.f32 %0, %1;" : "=f"(y) : "f"(x)); return y;
}
#define CPA(dst, src, sz) \
    asm volatile("cp.async.ca.shared.global [%0], [%1], 16, %2;" \
                 :: "r"(dst), "l"(src), "r"(sz) : "memory")
#define CP_COMMIT() asm volatile("cp.async.commit_group;" ::: "memory")
#define CP_WAIT1()  asm volatile("cp.async.wait_group 1;" ::: "memory")
#define CP_WAIT0()  asm volatile("cp.async.wait_group 0;" ::: "memory")

#define ASTR 40     // padded stride for [rows][32] bf16 tiles
#define BTSTR 136   // padded stride for [32][128] trans-B tiles

// fast e^x on FMA pipe
__device__ __forceinline__ float fast_exp(float x) {
    float y = x * 1.44269504089f;
    float n = rintf(y);
    float f = y - n;
    float p = 0.0096180489f;
    p = fmaf(p, f, 0.0555041087f);
    p = fmaf(p, f, 0.2402265069f);
    p = fmaf(p, f, 0.6931471806f);
    p = fmaf(p, f, 1.0f);
    int ni = (int)n;
    if (ni < -126) ni = -126;
    return __int_as_float((ni + 127) << 23) * p;
}

// ---------------- prep kernels ----------------
__global__ void k_gather(const int* __restrict__ text, const float* __restrict__ table) {
    int idx = blockIdx.x * blockDim.x + threadIdx.x;
    const int total = BB * SSL * (DD / 4);
    if (idx >= total) return;
    int d4 = idx & (DD / 4 - 1);
    int bs = idx >> 7;
    int tok = text[bs];
    float4 v = reinterpret_cast<const float4*>(table)[(size_t)tok * (DD / 4) + d4];
    __nv_bfloat162 h0 = __floats2bfloat162_rn(v.x, v.y);
    __nv_bfloat162 h1 = __floats2bfloat162_rn(v.z, v.w);
    uint2 o = make_uint2(*(uint32_t*)&h0, *(uint32_t*)&h1);
    *reinterpret_cast<uint2*>(g_xemb + (size_t)bs * DD + d4 * 4) = o;
}
__global__ void k_wprep(const float* __restrict__ w) {
    int idx = blockIdx.x * blockDim.x + threadIdx.x;
    if (idx >= JJ * KF * DD) return;
    int d = idx % DD;
    int k = (idx / DD) % KF;
    int j = idx / (DD * KF);
    g_wtT[idx] = __float2bfloat16(w[((size_t)k * DD + d) * JJ + j]);
}
__global__ void k_uprep(const float* __restrict__ u) {
    int idx = blockIdx.x * blockDim.x + threadIdx.x;
    if (idx >= CC * KF) return;
    g_Ubf[idx] = __float2bfloat16(u[idx]);
}

// ---------------- 1) conv as implicit GEMM: 128s x 64k tile, 3-stage ----------------
__global__ __launch_bounds__(256) void k_conv_mma(const float* __restrict__ convb) {
    extern __shared__ __align__(16) char dsm[];
    const uint32_t aA0 = smem_u32(dsm);                       // 3 x 128*ASTR bf16
    const uint32_t aB0 = aA0 + 3 * 128 * ASTR * 2;            // 3 x 64*ASTR bf16
    __shared__ float sbias[64];

    const int tid = threadIdx.x, wid = tid >> 5, lane = tid & 31;
    const int s0 = blockIdx.x * 128, k0 = blockIdx.y * 64, b = blockIdx.z;
    const int wm = (wid & 3) * 32, wn = (wid >> 2) * 32;
    if (tid < 64) sbias[tid] = convb[k0 + tid];

    float acc[2][4][4] = {};
    const int lrow = (lane & 7) + ((lane >> 3) & 1) * 8;
    const int lcol = ((lane >> 4) & 1) * 8;

    auto load_chunk = [&](int ch, int st) {
        const int j = ch >> 4, dc = ch & 15;
        const uint32_t aA = aA0 + st * (128 * ASTR * 2);
        const uint32_t aB = aB0 + st * (64 * ASTR * 2);
        #pragma unroll
        for (int it = 0; it < 3; it++) {
            int i = tid + it * 256;               // 768 = 512 A + 256 B
            if (i < 512) {
                int row = i >> 2, cs = i & 3;
                int g = s0 + row + j - PADW;
                unsigned ok = ((unsigned)g < SSL);
                const void* src = g_xemb + ((size_t)b * SSL + (ok ? g : 0)) * DD + dc * 32 + cs * 8;
                CPA(aA + (row * ASTR + cs * 8) * 2, src, ok ? 16u : 0u);
            } else {
                i -= 512;
                int row = i >> 2, cs = i & 3;
                const void* src = g_wtT + ((size_t)j * KF + k0 + row) * DD + dc * 32 + cs * 8;
                CPA(aB + (row * ASTR + cs * 8) * 2, src, 16u);
            }
        }
    };

    const int NC = JJ * 16;     // 144
    load_chunk(0, 0); CP_COMMIT();
    load_chunk(1, 1); CP_COMMIT();
    for (int ch = 0; ch < NC; ch++) {
        if (ch == NC - 1) CP_WAIT0(); else CP_WAIT1();
        __syncthreads();
        if (ch + 2 < NC) { load_chunk(ch + 2, (ch + 2) % 3); CP_COMMIT(); }
        const int st = ch % 3;
        const uint32_t aA = aA0 + st * (128 * ASTR * 2);
        const uint32_t aB = aB0 + st * (64 * ASTR * 2);
        #pragma unroll
        for (int ks = 0; ks < 2; ks++) {
            uint32_t a[2][4];
            #pragma unroll
            for (int mt = 0; mt < 2; mt++)
                ldsm_x4(a[mt][0], a[mt][1], a[mt][2], a[mt][3],
                        aA + ((wm + mt * 16 + lrow) * ASTR + ks * 16 + lcol) * 2);
            #pragma unroll
            for (int nt = 0; nt < 2; nt++) {
                uint32_t b0, b1, b2, b3;
                ldsm_x4(b0, b1, b2, b3,
                        aB + ((wn + nt * 16 + lrow) * ASTR + ks * 16 + lcol) * 2);
                #pragma unroll
                for (int mt = 0; mt < 2; mt++) {
                    mma_bf16(acc[mt][nt * 2 + 0], a[mt][0], a[mt][1], a[mt][2], a[mt][3], b0, b2);
                    mma_bf16(acc[mt][nt * 2 + 1], a[mt][0], a[mt][1], a[mt][2], a[mt][3], b1, b3);
                }
            }
        }
    }

    const int lr = lane >> 2, lc = (lane & 3) * 2;
    #pragma unroll
    for (int mt = 0; mt < 2; mt++)
        #pragma unroll
        for (int h = 0; h < 2; h++) {
            int s = s0 + wm + mt * 16 + lr + h * 8;
            __nv_bfloat16* orow = g_xf + ((size_t)b * SSL + s) * KF + k0;
            #pragma unroll
            for (int nt = 0; nt < 4; nt++) {
                int kc = wn + nt * 8 + lc;
                __nv_bfloat162 hh = __floats2bfloat162_rn(
                    htanh(acc[mt][nt][h * 2 + 0] + sbias[kc]),
                    htanh(acc[mt][nt][h * 2 + 1] + sbias[kc + 1]));
                *reinterpret_cast<uint32_t*>(orow + kc) = *(uint32_t*)&hh;
            }
        }
}

// ---------------- 2) scores = U @ xf^T -> bf16 (128c x 128s, 3-stage) ----------------
__global__ __launch_bounds__(256) void k_scores_mma() {
    extern __shared__ __align__(16) char dsm[];
    const uint32_t aA0 = smem_u32(dsm);                 // 3 x 128*ASTR
    const uint32_t aB0 = aA0 + 3 * 128 * ASTR * 2;      // 3 x 128*ASTR

    const int tid = threadIdx.x, wid = tid >> 5, lane = tid & 31;
    const int s0 = blockIdx.x * 128, c0 = blockIdx.y * 128, b = blockIdx.z;
    const int wm = (wid & 3) * 32, wn = (wid >> 2) * 64;
    const int lrow = (lane & 7) + ((lane >> 3) & 1) * 8;
    const int lcol = ((lane >> 4) & 1) * 8;

    float acc[2][8][4] = {};

    auto load_chunk = [&](int ch, int st) {
        const uint32_t aA = aA0 + st * (128 * ASTR * 2);
        const uint32_t aB = aB0 + st * (128 * ASTR * 2);
        #pragma unroll
        for (int it = 0; it < 2; it++) {
            int i = tid + it * 256;
            int row = i >> 2, cs = i & 3;
            uint32_t doff = (row * ASTR + cs * 8) * 2;
            const void* sA = g_Ubf + (size_t)(c0 + row) * KF + ch * 32 + cs * 8;
            CPA(aA + doff, sA, 16u);
            const void* sB = g_xf + ((size_t)b * SSL + s0 + row) * KF + ch * 32 + cs * 8;
            CPA(aB + doff, sB, 16u);
        }
    };

    const int NC = KF / 32;        // 8
    load_chunk(0, 0); CP_COMMIT();
    load_chunk(1, 1); CP_COMMIT();
    for (int ch = 0; ch < NC; ch++) {
        if (ch == NC - 1) CP_WAIT0(); else CP_WAIT1();
        __syncthreads();
        if (ch + 2 < NC) { load_chunk(ch + 2, (ch + 2) % 3); CP_COMMIT(); }
        const int st = ch % 3;
        const uint32_t aA = aA0 + st * (128 * ASTR * 2);
        const uint32_t aB = aB0 + st * (128 * ASTR * 2);
        #pragma unroll
        for (int ks = 0; ks < 2; ks++) {
            uint32_t a[2][4];
            #pragma unroll
            for (int mt = 0; mt < 2; mt++)
                ldsm_x4(a[mt][0], a[mt][1], a[mt][2], a[mt][3],
                        aA + ((wm + mt * 16 + lrow) * ASTR + ks * 16 + lcol) * 2);
            #pragma unroll
            for (int nt = 0; nt < 4; nt++) {
                uint32_t b0, b1, b2, b3;
                ldsm_x4(b0, b1, b2, b3,
                        aB + ((wn + nt * 16 + lrow) * ASTR + ks * 16 + lcol) * 2);
                #pragma unroll
                for (int mt = 0; mt < 2; mt++) {
                    mma_bf16(acc[mt][nt * 2 + 0], a[mt][0], a[mt][1], a[mt][2], a[mt][3], b0, b2);
                    mma_bf16(acc[mt][nt * 2 + 1], a[mt][0], a[mt][1], a[mt][2], a[mt][3], b1, b3);
                }
            }
        }
    }

    const int lr = lane >> 2, lc = (lane & 3) * 2;
    #pragma unroll
    for (int mt = 0; mt < 2; mt++)
        #pragma unroll
        for (int h = 0; h < 2; h++) {
            int c = c0 + wm + mt * 16 + lr + h * 8;
            __nv_bfloat16* orow = g_sc + ((size_t)b * CC + c) * SSL + s0;
            #pragma unroll
            for (int nt = 0; nt < 8; nt++) {
                int sc = wn + nt * 8 + lc;
                __nv_bfloat162 hh = __floats2bfloat162_rn(acc[mt][nt][h * 2 + 0],
                                                          acc[mt][nt][h * 2 + 1]);
                *reinterpret_cast<uint32_t*>(orow + sc) = *(uint32_t*)&hh;
            }
        }
}

// ---------------- 3) row max + in-place expify + row sum (shuffle reduce) ----------------
__global__ void k_stats() {
    __shared__ float red[8];
    const int row = blockIdx.x;
    const int tid = threadIdx.x, lane = tid & 31, wid = tid >> 5;
    __nv_bfloat16* p = g_sc + (size_t)row * SSL + tid * 8;
    uint4 v = *reinterpret_cast<const uint4*>(p);
    float x[8];
    {
        uint32_t* u = (uint32_t*)&v;
        #pragma unroll
        for (int w = 0; w < 4; w++) {
            __nv_bfloat162 h = *reinterpret_cast<__nv_bfloat162*>(&u[w]);
            x[2 * w]     = __low2float(h);
            x[2 * w + 1] = __high2float(h);
        }
    }
    float mx = x[0];
    #pragma unroll
    for (int i = 1; i < 8; i++) mx = fmaxf(mx, x[i]);
    #pragma unroll
    for (int o = 16; o > 0; o >>= 1) mx = fmaxf(mx, __shfl_xor_sync(0xffffffffu, mx, o));
    if (lane == 0) red[wid] = mx;
    __syncthreads();
    mx = red[0];
    #pragma unroll
    for (int i = 1; i < 8; i++) mx = fmaxf(mx, red[i]);
    __syncthreads();

    uint4 o4; uint32_t* ou = (uint32_t*)&o4;
    float sm = 0.f;
    #pragma unroll
    for (int w = 0; w < 4; w++) {
        float e0 = fast_exp(x[2 * w] - mx);
        float e1 = fast_exp(x[2 * w + 1] - mx);
        __nv_bfloat16 b0 = __float2bfloat16(e0);
        __nv_bfloat16 b1 = __float2bfloat16(e1);
        sm += __bfloat162float(b0) + __bfloat162float(b1);
        __nv_bfloat162 hh; hh.x = b0; hh.y = b1;
        ou[w] = *(uint32_t*)&hh;
    }
    *reinterpret_cast<uint4*>(p) = o4;
    #pragma unroll
    for (int o = 16; o > 0; o >>= 1) sm += __shfl_xor_sync(0xffffffffu, sm, o);
    if (lane == 0) red[wid] = sm;
    __syncthreads();
    if (tid == 0) {
        float t = 0.f;
        #pragma unroll
        for (int i = 0; i < 8; i++) t += red[i];
        g_l[row] = t;
    }
}

// ---------------- 4) m = alpha @ xf (B via ldmatrix.trans), scaled by 1/l ----------------
__global__ __launch_bounds__(256) void k_mgemm_mma() {
    extern __shared__ __align__(16) char dsm[];
    const uint32_t aA0 = smem_u32(dsm);                 // 3 x 128*ASTR  (alpha [c][s])
    const uint32_t aB0 = aA0 + 3 * 128 * ASTR * 2;      // 3 x 32*BTSTR  (xf [s][k])
    __shared__ float s_l[128];

    const int tid = threadIdx.x, wid = tid >> 5, lane = tid & 31;
    const int k0 = blockIdx.x * 128, c0 = blockIdx.y * 128, b = blockIdx.z;
    const int wm = (wid & 3) * 32, wn = (wid >> 2) * 64;
    if (tid < 128) s_l[tid] = g_l[(size_t)b * CC + c0 + tid];

    const int lrow = (lane & 7) + ((lane >> 3) & 1) * 8;
    const int lcol = ((lane >> 4) & 1) * 8;
    const int tkrow = (lane & 7) + ((lane >> 4) & 1) * 8;   // trans: s row
    const int tncol = ((lane >> 3) & 1) * 8;                // trans: kf col

    float acc[2][8][4] = {};

    auto load_chunk = [&](int ch, int st) {
        const uint32_t aA = aA0 + st * (128 * ASTR * 2);
        const uint32_t aB = aB0 + st * (32 * BTSTR * 2);
        #pragma unroll
        for (int it = 0; it < 2; it++) {
            int i = tid + it * 256;
            int row = i >> 2, cs = i & 3;
            const void* sA = g_sc + ((size_t)b * CC + c0 + row) * SSL + ch * 32 + cs * 8;
            CPA(aA + (row * ASTR + cs * 8) * 2, sA, 16u);
        }
        // B: 32 rows x 128 cols = 512 x 16B chunks -> 2 per thread  (R6 BUG: was 256)
        #pragma unroll
        for (int it = 0; it < 2; it++) {
            int i = tid + it * 256;
            int row = i >> 4, c8 = i & 15;
            const void* sB = g_xf + ((size_t)b * SSL + ch * 32 + row) * KF + k0 + c8 * 8;
            CPA(aB + (row * BTSTR + c8 * 8) * 2, sB, 16u);
        }
    };

    const int NC = SSL / 32;       // 64
    load_chunk(0, 0); CP_COMMIT();
    load_chunk(1, 1); CP_COMMIT();
    for (int ch = 0; ch < NC; ch++) {
        if (ch == NC - 1) CP_WAIT0(); else CP_WAIT1();
        __syncthreads();
        if (ch + 2 < NC) { load_chunk(ch + 2, (ch + 2) % 3); CP_COMMIT(); }
        const int st = ch % 3;
        const uint32_t aA = aA0 + st * (128 * ASTR * 2);
        const uint32_t aB = aB0 + st * (32 * BTSTR * 2);
        #pragma unroll
        for (int ks = 0; ks < 2; ks++) {
            uint32_t a[2][4];
            #pragma unroll
            for (int mt = 0; mt < 2; mt++)
                ldsm_x4(a[mt][0], a[mt][1], a[mt][2], a[mt][3],
                        aA + ((wm + mt * 16 + lrow) * ASTR + ks * 16 + lcol) * 2);
            #pragma unroll
            for (int nt = 0; nt < 4; nt++) {
                uint32_t b0, b1, b2, b3;
                ldsm_x4_t(b0, b1, b2, b3,
                          aB + ((ks * 16 + tkrow) * BTSTR + wn + nt * 16 + tncol) * 2);
                #pragma unroll
                for (int mt = 0; mt < 2; mt++) {
                    mma_bf16(acc[mt][nt * 2 + 0], a[mt][0], a[mt][1], a[mt][2], a[mt][3], b0, b2);
                    mma_bf16(acc[mt][nt * 2 + 1], a[mt][0], a[mt][1], a[mt][2], a[mt][3], b1, b3);
                }
            }
        }
    }

    const int lr = lane >> 2, lc = (lane & 3) * 2;
    #pragma unroll
    for (int mt = 0; mt < 2; mt++)
        #pragma unroll
        for (int h = 0; h < 2; h++) {
            int cidx = wm + mt * 16 + lr + h * 8;
            float rl = 1.f / s_l[cidx];
            float* orow = g_m + ((size_t)b * CC + c0 + cidx) * KF + k0;
            #pragma unroll
            for (int nt = 0; nt < 8; nt++) {
                int kc = wn + nt * 8 + lc;
                float2 o = make_float2(acc[mt][nt][h * 2 + 0] * rl,
                                       acc[mt][nt][h * 2 + 1] * rl);
                *reinterpret_cast<float2*>(orow + kc) = o;
            }
        }
}

// ---------------- 5) final readout ----------------
__global__ void k_final(const float* __restrict__ fw, const float* __restrict__ fb,
                        float* __restrict__ out) {
    int gwarp = (blockIdx.x * blockDim.x + threadIdx.x) >> 5;
    int lane  = threadIdx.x & 31;
    if (gwarp >= BB * CC) return;
    int c = gwarp % CC;
    const float* m = g_m + (size_t)gwarp * KF;
    const float* w = fw + (size_t)c * KF;
    float acc = 0.f;
    #pragma unroll
    for (int k = lane; k < KF; k += 32) acc += w[k] * m[k];
    #pragma unroll
    for (int o = 16; o > 0; o >>= 1) acc += __shfl_down_sync(0xffffffff, acc, o);
    if (lane == 0) out[gwarp] = acc + fb[c];
}

// ---------------------------------------------------------------------------
extern "C" void kernel_launch(void* const* d_in, const int* in_sizes, int n_in,
                              void* d_out, int out_size) {
    const int*   text  = (const int*)  d_in[0];
    const float* table = (const float*)d_in[1];
    const float* convw = (const float*)d_in[2];
    const float* convb = (const float*)d_in[3];
    const float* Uw    = (const float*)d_in[4];
    const float* fw    = (const float*)d_in[5];
    const float* fb    = (const float*)d_in[6];
    float* out = (float*)d_out;

    const int SM_CONV   = 3 * 128 * ASTR * 2 + 3 * 64 * ASTR * 2;    // 46080
    const int SM_SCORES = 2 * (3 * 128 * ASTR * 2);                  // 61440
    const int SM_MGEMM  = 3 * 128 * ASTR * 2 + 3 * 32 * BTSTR * 2;   // 56832
    static int attr_done = 0;
    if (!attr_done) {
        cudaFuncSetAttribute(k_conv_mma,   cudaFuncAttributeMaxDynamicSharedMemorySize, SM_CONV);
        cudaFuncSetAttribute(k_scores_mma, cudaFuncAttributeMaxDynamicSharedMemorySize, SM_SCORES);
        cudaFuncSetAttribute(k_mgemm_mma,  cudaFuncAttributeMaxDynamicSharedMemorySize, SM_MGEMM);
        attr_done = 1;
    }

    k_gather<<<(BB*SSL*(DD/4) + 255) / 256, 256>>>(text, table);
    k_wprep <<<(JJ*KF*DD + 255) / 256, 256>>>(convw);
    k_uprep <<<(CC*KF + 255) / 256, 256>>>(Uw);
    k_conv_mma  <<<dim3(SSL/128, KF/64, BB), 256, SM_CONV>>>(convb);
    k_scores_mma<<<dim3(SSL/128, CC/128, BB), 256, SM_SCORES>>>();
    k_stats     <<<BB*CC, 256>>>();
    k_mgemm_mma <<<dim3(KF/128, CC/128, BB), 256, SM_MGEMM>>>();
    k_final     <<<(BB*CC*32) / 256, 256>>>(fw, fb, out);
}

// round 16
// speedup vs baseline: 7.0954x; 1.1283x over previous
#include <cuda_runtime.h>
#include <cuda_bf16.h>
#include <math.h>
#include <stdint.h>

#define BB   8
#define SSL  2048
#define DD   512
#define KF   256      // n_kernels
#define JJ   9
#define CC   4096
#define PADW 4

// ---------------- static device scratch (allocation-free rule) ----------------
__device__ __nv_bfloat16 g_xemb [(size_t)BB*SSL*DD];   // 16 MB
__device__ __nv_bfloat16 g_wtT  [(size_t)JJ*KF*DD];    // 2.25 MB [j][k][d]
__device__ __nv_bfloat16 g_Ubf  [(size_t)CC*KF];       // 2 MB
__device__ __nv_bfloat16 g_xf   [(size_t)BB*SSL*KF];   // 8 MB  [b][s][k]
__device__ __nv_bfloat16 g_sc   [(size_t)BB*CC*SSL];   // 128 MB alpha_unnorm (bf16)
__device__ float         g_l    [(size_t)BB*CC];       // softmax denominators (atomic acc)
__device__ float         g_m    [(size_t)BB*CC*KF];    // 32 MB

// ---------------- PTX helpers (base-ISA only) ----------------
__device__ __forceinline__ uint32_t smem_u32(const void* p) {
    uint32_t a;
    asm("{ .reg .u64 t; cvta.to.shared.u64 t, %1; cvt.u32.u64 %0, t; }" : "=r"(a) : "l"(p));
    return a;
}
__device__ __forceinline__ void ldsm_x4(uint32_t& r0, uint32_t& r1, uint32_t& r2, uint32_t& r3,
                                        uint32_t addr) {
    asm volatile("ldmatrix.sync.aligned.m8n8.x4.shared.b16 {%0,%1,%2,%3}, [%4];"
                 : "=r"(r0), "=r"(r1), "=r"(r2), "=r"(r3) : "r"(addr));
}
__device__ __forceinline__ void ldsm_x4_t(uint32_t& r0, uint32_t& r1, uint32_t& r2, uint32_t& r3,
                                          uint32_t addr) {
    asm volatile("ldmatrix.sync.aligned.m8n8.x4.trans.shared.b16 {%0,%1,%2,%3}, [%4];"
                 : "=r"(r0), "=r"(r1), "=r"(r2), "=r"(r3) : "r"(addr));
}
__device__ __forceinline__ void mma_bf16(float* c, uint32_t a0, uint32_t a1, uint32_t a2,
                                         uint32_t a3, uint32_t b0, uint32_t b1) {
    asm volatile("mma.sync.aligned.m16n8k16.row.col.f32.bf16.bf16.f32 "
                 "{%0,%1,%2,%3}, {%4,%5,%6,%7}, {%8,%9}, {%0,%1,%2,%3};"
                 : "+f"(c[0]), "+f"(c[1]), "+f"(c[2]), "+f"(c[3])
                 : "r"(a0), "r"(a1), "r"(a2), "r"(a3), "r"(b0), "r"(b1));
}
__device__ __forceinline__ float htanh(float x) {
    float y; asm("tanh.approx.f32 %0, %1;" : "=f"(y) : "f"(x)); return y;
}
#define CPA(dst, src, sz) \
    asm volatile("cp.async.ca.shared.global [%0], [%1], 16, %2;" \
                 :: "r"(dst), "l"(src), "r"(sz) : "memory")
#define CP_COMMIT() asm volatile("cp.async.commit_group;" ::: "memory")
#define CP_WAIT1()  asm volatile("cp.async.wait_group 1;" ::: "memory")
#define CP_WAIT0()  asm volatile("cp.async.wait_group 0;" ::: "memory")

#define ASTR 40     // padded stride for [rows][32] bf16 tiles
#define BTSTR 136   // padded stride for [32][128] trans-B tiles

// fast e^x on FMA pipe
__device__ __forceinline__ float fast_exp(float x) {
    float y = x * 1.44269504089f;
    float n = rintf(y);
    float f = y - n;
    float p = 0.0096180489f;
    p = fmaf(p, f, 0.0555041087f);
    p = fmaf(p, f, 0.2402265069f);
    p = fmaf(p, f, 0.6931471806f);
    p = fmaf(p, f, 1.0f);
    int ni = (int)n;
    if (ni < -126) ni = -126;
    if (ni >  127) ni =  127;
    return __int_as_float((ni + 127) << 23) * p;
}

// ---------------- prep kernels ----------------
__global__ void k_gather(const int* __restrict__ text, const float* __restrict__ table) {
    int idx = blockIdx.x * blockDim.x + threadIdx.x;
    const int total = BB * SSL * (DD / 4);
    if (idx >= total) return;
    int d4 = idx & (DD / 4 - 1);
    int bs = idx >> 7;
    int tok = text[bs];
    float4 v = reinterpret_cast<const float4*>(table)[(size_t)tok * (DD / 4) + d4];
    __nv_bfloat162 h0 = __floats2bfloat162_rn(v.x, v.y);
    __nv_bfloat162 h1 = __floats2bfloat162_rn(v.z, v.w);
    uint2 o = make_uint2(*(uint32_t*)&h0, *(uint32_t*)&h1);
    *reinterpret_cast<uint2*>(g_xemb + (size_t)bs * DD + d4 * 4) = o;
}
__global__ void k_wprep(const float* __restrict__ w) {
    int idx = blockIdx.x * blockDim.x + threadIdx.x;
    if (idx >= JJ * KF * DD) return;
    int d = idx % DD;
    int k = (idx / DD) % KF;
    int j = idx / (DD * KF);
    g_wtT[idx] = __float2bfloat16(w[((size_t)k * DD + d) * JJ + j]);
}
__global__ void k_uprep(const float* __restrict__ u) {
    int idx = blockIdx.x * blockDim.x + threadIdx.x;
    if (idx >= CC * KF) return;
    g_Ubf[idx] = __float2bfloat16(u[idx]);
}
__global__ void k_zerol() {
    int idx = blockIdx.x * blockDim.x + threadIdx.x;
    if (idx < BB * CC) g_l[idx] = 0.f;
}

// ---------------- 1) conv: halo-A implicit GEMM, 3 taps per chunk ----------------
// A stage: 136 rows (s0-4 .. s0+131) x 32 d.  B stage: 3 taps x 64 k x 32 d.
// chunk ch = dc*3 + jg; taps j = jg*3 + {0,1,2}; A read with row offset +j.
#define CONV_A_ROWS 136
#define CONV_A_STG  (CONV_A_ROWS * ASTR * 2)          // 10880
#define CONV_B_STG  (192 * ASTR * 2)                  // 15360

__global__ __launch_bounds__(256) void k_conv_mma(const float* __restrict__ convb) {
    extern __shared__ __align__(16) char dsm[];
    const uint32_t aA0 = smem_u32(dsm);               // 3 stages A
    const uint32_t aB0 = aA0 + 3 * CONV_A_STG;        // 3 stages B
    __shared__ float sbias[64];

    const int tid = threadIdx.x, wid = tid >> 5, lane = tid & 31;
    const int s0 = blockIdx.x * 128, k0 = blockIdx.y * 64, b = blockIdx.z;
    const int wm = (wid & 3) * 32, wn = (wid >> 2) * 32;
    if (tid < 64) sbias[tid] = convb[k0 + tid];

    float acc[2][4][4] = {};
    const int lrow = (lane & 7) + ((lane >> 3) & 1) * 8;
    const int lcol = ((lane >> 4) & 1) * 8;

    auto load_chunk = [&](int ch, int st) {
        const int dc = ch / 3, jg = ch % 3;
        const uint32_t aA = aA0 + st * CONV_A_STG;
        const uint32_t aB = aB0 + st * CONV_B_STG;
        // A: 136 rows x 32 cols = 544 x 16B;  B: 3*64 rows x 32 = 768 x 16B; total 1312
        for (int i = tid; i < 1312; i += 256) {
            if (i < 544) {
                int row = i >> 2, cs = i & 3;
                int g = s0 - PADW + row;
                unsigned ok = ((unsigned)g < SSL);
                const void* src = g_xemb + ((size_t)b * SSL + (ok ? g : 0)) * DD + dc * 32 + cs * 8;
                CPA(aA + (row * ASTR + cs * 8) * 2, src, ok ? 16u : 0u);
            } else {
                int idx = i - 544;
                int jl = idx >> 8;                  // 0..2
                int rem = idx & 255;
                int row = rem >> 2, cs = rem & 3;
                int j = jg * 3 + jl;
                const void* src = g_wtT + ((size_t)j * KF + k0 + row) * DD + dc * 32 + cs * 8;
                CPA(aB + ((jl * 64 + row) * ASTR + cs * 8) * 2, src, 16u);
            }
        }
    };

    const int NC = (DD / 32) * 3;     // 48
    load_chunk(0, 0); CP_COMMIT();
    load_chunk(1, 1); CP_COMMIT();
    for (int ch = 0; ch < NC; ch++) {
        if (ch == NC - 1) CP_WAIT0(); else CP_WAIT1();
        __syncthreads();
        if (ch + 2 < NC) { load_chunk(ch + 2, (ch + 2) % 3); CP_COMMIT(); }
        const int st = ch % 3;
        const int jg = ch % 3;            // tap group of THIS chunk (ch = dc*3 + jg)
        const uint32_t aA = aA0 + st * CONV_A_STG;
        const uint32_t aB = aB0 + st * CONV_B_STG;
        #pragma unroll
        for (int jl = 0; jl < 3; jl++) {
            const int j = jg * 3 + jl;    // full tap index 0..8 -> A row shift
            #pragma unroll
            for (int ks = 0; ks < 2; ks++) {
                uint32_t a[2][4];
                #pragma unroll
                for (int mt = 0; mt < 2; mt++)
                    ldsm_x4(a[mt][0], a[mt][1], a[mt][2], a[mt][3],
                            aA + ((wm + mt * 16 + lrow + j) * ASTR + ks * 16 + lcol) * 2);
                #pragma unroll
                for (int nt = 0; nt < 2; nt++) {
                    uint32_t b0, b1, b2, b3;
                    ldsm_x4(b0, b1, b2, b3,
                            aB + ((jl * 64 + wn + nt * 16 + lrow) * ASTR + ks * 16 + lcol) * 2);
                    #pragma unroll
                    for (int mt = 0; mt < 2; mt++) {
                        mma_bf16(acc[mt][nt * 2 + 0], a[mt][0], a[mt][1], a[mt][2], a[mt][3], b0, b2);
                        mma_bf16(acc[mt][nt * 2 + 1], a[mt][0], a[mt][1], a[mt][2], a[mt][3], b1, b3);
                    }
                }
            }
        }
    }

    const int lr = lane >> 2, lc = (lane & 3) * 2;
    #pragma unroll
    for (int mt = 0; mt < 2; mt++)
        #pragma unroll
        for (int h = 0; h < 2; h++) {
            int s = s0 + wm + mt * 16 + lr + h * 8;
            __nv_bfloat16* orow = g_xf + ((size_t)b * SSL + s) * KF + k0;
            #pragma unroll
            for (int nt = 0; nt < 4; nt++) {
                int kc = wn + nt * 8 + lc;
                __nv_bfloat162 hh = __floats2bfloat162_rn(
                    htanh(acc[mt][nt][h * 2 + 0] + sbias[kc]),
                    htanh(acc[mt][nt][h * 2 + 1] + sbias[kc + 1]));
                *reinterpret_cast<uint32_t*>(orow + kc) = *(uint32_t*)&hh;
            }
        }
}

// ---------------- 2) scores = U @ xf^T -> exp() -> bf16 alpha + row sums ----------------
__global__ __launch_bounds__(256) void k_scores_mma() {
    extern __shared__ __align__(16) char dsm[];
    const uint32_t aA0 = smem_u32(dsm);                 // 3 x 128*ASTR
    const uint32_t aB0 = aA0 + 3 * 128 * ASTR * 2;      // 3 x 128*ASTR

    const int tid = threadIdx.x, wid = tid >> 5, lane = tid & 31;
    const int s0 = blockIdx.x * 128, c0 = blockIdx.y * 128, b = blockIdx.z;
    const int wm = (wid & 3) * 32, wn = (wid >> 2) * 64;
    const int lrow = (lane & 7) + ((lane >> 3) & 1) * 8;
    const int lcol = ((lane >> 4) & 1) * 8;

    float acc[2][8][4] = {};

    auto load_chunk = [&](int ch, int st) {
        const uint32_t aA = aA0 + st * (128 * ASTR * 2);
        const uint32_t aB = aB0 + st * (128 * ASTR * 2);
        #pragma unroll
        for (int it = 0; it < 2; it++) {
            int i = tid + it * 256;
            int row = i >> 2, cs = i & 3;
            uint32_t doff = (row * ASTR + cs * 8) * 2;
            const void* sA = g_Ubf + (size_t)(c0 + row) * KF + ch * 32 + cs * 8;
            CPA(aA + doff, sA, 16u);
            const void* sB = g_xf + ((size_t)b * SSL + s0 + row) * KF + ch * 32 + cs * 8;
            CPA(aB + doff, sB, 16u);
        }
    };

    const int NC = KF / 32;        // 8
    load_chunk(0, 0); CP_COMMIT();
    load_chunk(1, 1); CP_COMMIT();
    for (int ch = 0; ch < NC; ch++) {
        if (ch == NC - 1) CP_WAIT0(); else CP_WAIT1();
        __syncthreads();
        if (ch + 2 < NC) { load_chunk(ch + 2, (ch + 2) % 3); CP_COMMIT(); }
        const int st = ch % 3;
        const uint32_t aA = aA0 + st * (128 * ASTR * 2);
        const uint32_t aB = aB0 + st * (128 * ASTR * 2);
        #pragma unroll
        for (int ks = 0; ks < 2; ks++) {
            uint32_t a[2][4];
            #pragma unroll
            for (int mt = 0; mt < 2; mt++)
                ldsm_x4(a[mt][0], a[mt][1], a[mt][2], a[mt][3],
                        aA + ((wm + mt * 16 + lrow) * ASTR + ks * 16 + lcol) * 2);
            #pragma unroll
            for (int nt = 0; nt < 4; nt++) {
                uint32_t b0, b1, b2, b3;
                ldsm_x4(b0, b1, b2, b3,
                        aB + ((wn + nt * 16 + lrow) * ASTR + ks * 16 + lcol) * 2);
                #pragma unroll
                for (int mt = 0; mt < 2; mt++) {
                    mma_bf16(acc[mt][nt * 2 + 0], a[mt][0], a[mt][1], a[mt][2], a[mt][3], b0, b2);
                    mma_bf16(acc[mt][nt * 2 + 1], a[mt][0], a[mt][1], a[mt][2], a[mt][3], b1, b3);
                }
            }
        }
    }

    // epilogue: alpha = exp(score) (no max shift; scores bounded), bf16 write,
    // accumulate row sums of the bf16-rounded values.
    const int lr = lane >> 2, lc = (lane & 3) * 2;
    #pragma unroll
    for (int mt = 0; mt < 2; mt++)
        #pragma unroll
        for (int h = 0; h < 2; h++) {
            int c = c0 + wm + mt * 16 + lr + h * 8;
            __nv_bfloat16* orow = g_sc + ((size_t)b * CC + c) * SSL + s0;
            float rsum = 0.f;
            #pragma unroll
            for (int nt = 0; nt < 8; nt++) {
                int sc = wn + nt * 8 + lc;
                float e0 = fast_exp(acc[mt][nt][h * 2 + 0]);
                float e1 = fast_exp(acc[mt][nt][h * 2 + 1]);
                __nv_bfloat16 b0 = __float2bfloat16(e0);
                __nv_bfloat16 b1 = __float2bfloat16(e1);
                rsum += __bfloat162float(b0) + __bfloat162float(b1);
                __nv_bfloat162 hh; hh.x = b0; hh.y = b1;
                *reinterpret_cast<uint32_t*>(orow + sc) = *(uint32_t*)&hh;
            }
            rsum += __shfl_xor_sync(0xffffffffu, rsum, 1);
            rsum += __shfl_xor_sync(0xffffffffu, rsum, 2);
            if ((lane & 3) == 0) atomicAdd(&g_l[(size_t)b * CC + c], rsum);
        }
}

// ---------------- 3) m = alpha @ xf (B via ldmatrix.trans), scaled by 1/l ----------------
__global__ __launch_bounds__(256) void k_mgemm_mma() {
    extern __shared__ __align__(16) char dsm[];
    const uint32_t aA0 = smem_u32(dsm);                 // 3 x 128*ASTR  (alpha [c][s])
    const uint32_t aB0 = aA0 + 3 * 128 * ASTR * 2;      // 3 x 32*BTSTR  (xf [s][k])
    __shared__ float s_l[128];

    const int tid = threadIdx.x, wid = tid >> 5, lane = tid & 31;
    const int k0 = blockIdx.x * 128, c0 = blockIdx.y * 128, b = blockIdx.z;
    const int wm = (wid & 3) * 32, wn = (wid >> 2) * 64;
    if (tid < 128) s_l[tid] = g_l[(size_t)b * CC + c0 + tid];

    const int lrow = (lane & 7) + ((lane >> 3) & 1) * 8;
    const int lcol = ((lane >> 4) & 1) * 8;
    const int tkrow = (lane & 7) + ((lane >> 4) & 1) * 8;
    const int tncol = ((lane >> 3) & 1) * 8;

    float acc[2][8][4] = {};

    auto load_chunk = [&](int ch, int st) {
        const uint32_t aA = aA0 + st * (128 * ASTR * 2);
        const uint32_t aB = aB0 + st * (32 * BTSTR * 2);
        #pragma unroll
        for (int it = 0; it < 2; it++) {
            int i = tid + it * 256;
            int row = i >> 2, cs = i & 3;
            const void* sA = g_sc + ((size_t)b * CC + c0 + row) * SSL + ch * 32 + cs * 8;
            CPA(aA + (row * ASTR + cs * 8) * 2, sA, 16u);
        }
        #pragma unroll
        for (int it = 0; it < 2; it++) {
            int i = tid + it * 256;
            int row = i >> 4, c8 = i & 15;
            const void* sB = g_xf + ((size_t)b * SSL + ch * 32 + row) * KF + k0 + c8 * 8;
            CPA(aB + (row * BTSTR + c8 * 8) * 2, sB, 16u);
        }
    };

    const int NC = SSL / 32;       // 64
    load_chunk(0, 0); CP_COMMIT();
    load_chunk(1, 1); CP_COMMIT();
    for (int ch = 0; ch < NC; ch++) {
        if (ch == NC - 1) CP_WAIT0(); else CP_WAIT1();
        __syncthreads();
        if (ch + 2 < NC) { load_chunk(ch + 2, (ch + 2) % 3); CP_COMMIT(); }
        const int st = ch % 3;
        const uint32_t aA = aA0 + st * (128 * ASTR * 2);
        const uint32_t aB = aB0 + st * (32 * BTSTR * 2);
        #pragma unroll
        for (int ks = 0; ks < 2; ks++) {
            uint32_t a[2][4];
            #pragma unroll
            for (int mt = 0; mt < 2; mt++)
                ldsm_x4(a[mt][0], a[mt][1], a[mt][2], a[mt][3],
                        aA + ((wm + mt * 16 + lrow) * ASTR + ks * 16 + lcol) * 2);
            #pragma unroll
            for (int nt = 0; nt < 4; nt++) {
                uint32_t b0, b1, b2, b3;
                ldsm_x4_t(b0, b1, b2, b3,
                          aB + ((ks * 16 + tkrow) * BTSTR + wn + nt * 16 + tncol) * 2);
                #pragma unroll
                for (int mt = 0; mt < 2; mt++) {
                    mma_bf16(acc[mt][nt * 2 + 0], a[mt][0], a[mt][1], a[mt][2], a[mt][3], b0, b2);
                    mma_bf16(acc[mt][nt * 2 + 1], a[mt][0], a[mt][1], a[mt][2], a[mt][3], b1, b3);
                }
            }
        }
    }

    const int lr = lane >> 2, lc = (lane & 3) * 2;
    #pragma unroll
    for (int mt = 0; mt < 2; mt++)
        #pragma unroll
        for (int h = 0; h < 2; h++) {
            int cidx = wm + mt * 16 + lr + h * 8;
            float rl = 1.f / s_l[cidx];
            float* orow = g_m + ((size_t)b * CC + c0 + cidx) * KF + k0;
            #pragma unroll
            for (int nt = 0; nt < 8; nt++) {
                int kc = wn + nt * 8 + lc;
                float2 o = make_float2(acc[mt][nt][h * 2 + 0] * rl,
                                       acc[mt][nt][h * 2 + 1] * rl);
                *reinterpret_cast<float2*>(orow + kc) = o;
            }
        }
}

// ---------------- 4) final readout ----------------
__global__ void k_final(const float* __restrict__ fw, const float* __restrict__ fb,
                        float* __restrict__ out) {
    int gwarp = (blockIdx.x * blockDim.x + threadIdx.x) >> 5;
    int lane  = threadIdx.x & 31;
    if (gwarp >= BB * CC) return;
    int c = gwarp % CC;
    const float* m = g_m + (size_t)gwarp * KF;
    const float* w = fw + (size_t)c * KF;
    float acc = 0.f;
    #pragma unroll
    for (int k = lane; k < KF; k += 32) acc += w[k] * m[k];
    #pragma unroll
    for (int o = 16; o > 0; o >>= 1) acc += __shfl_down_sync(0xffffffff, acc, o);
    if (lane == 0) out[gwarp] = acc + fb[c];
}

// ---------------------------------------------------------------------------
extern "C" void kernel_launch(void* const* d_in, const int* in_sizes, int n_in,
                              void* d_out, int out_size) {
    const int*   text  = (const int*)  d_in[0];
    const float* table = (const float*)d_in[1];
    const float* convw = (const float*)d_in[2];
    const float* convb = (const float*)d_in[3];
    const float* Uw    = (const float*)d_in[4];
    const float* fw    = (const float*)d_in[5];
    const float* fb    = (const float*)d_in[6];
    float* out = (float*)d_out;

    const int SM_CONV   = 3 * (CONV_A_STG + CONV_B_STG);             // 78720
    const int SM_SCORES = 2 * (3 * 128 * ASTR * 2);                  // 61440
    const int SM_MGEMM  = 3 * 128 * ASTR * 2 + 3 * 32 * BTSTR * 2;   // 56832
    static int attr_done = 0;
    if (!attr_done) {
        cudaFuncSetAttribute(k_conv_mma,   cudaFuncAttributeMaxDynamicSharedMemorySize, SM_CONV);
        cudaFuncSetAttribute(k_scores_mma, cudaFuncAttributeMaxDynamicSharedMemorySize, SM_SCORES);
        cudaFuncSetAttribute(k_mgemm_mma,  cudaFuncAttributeMaxDynamicSharedMemorySize, SM_MGEMM);
        attr_done = 1;
    }

    k_gather<<<(BB*SSL*(DD/4) + 255) / 256, 256>>>(text, table);
    k_wprep <<<(JJ*KF*DD + 255) / 256, 256>>>(convw);
    k_uprep <<<(CC*KF + 255) / 256, 256>>>(Uw);
    k_zerol <<<(BB*CC + 255) / 256, 256>>>();
    k_conv_mma  <<<dim3(SSL/128, KF/64, BB), 256, SM_CONV>>>(convb);
    k_scores_mma<<<dim3(SSL/128, CC/128, BB), 256, SM_SCORES>>>();
    k_mgemm_mma <<<dim3(KF/128, CC/128, BB), 256, SM_MGEMM>>>();
    k_final     <<<(BB*CC*32) / 256, 256>>>(fw, fb, out);
}